// round 17
// baseline (speedup 1.0000x reference)
#include <cuda_runtime.h>
#include <cstdint>

#define NN 10000
#define EE 320000

__device__ unsigned g_h1[(size_t)NN*256*32];
__device__ unsigned g_l1[(size_t)NN*256*32];
__device__ unsigned g_h0[(size_t)NN*64*32];
__device__ unsigned g_l0[(size_t)NN*64*32];
__device__ float g_cf[NN*64];
__device__ float g_nA[NN*64];
__device__ float g_nB[NN*64];
__device__ float g_agg[NN*64];
__device__ float g_edge[(size_t)EE*64];

__device__ __align__(16) uint2 g_wf[87552];

__device__ __forceinline__ unsigned packbf(float lo,float hi){
  unsigned r;asm("cvt.rn.bf16x2.f32 %0,%1,%2;":"=r"(r):"f"(hi),"f"(lo));return r;}
__device__ __forceinline__ float bflo(unsigned p){return __uint_as_float(p<<16);}
__device__ __forceinline__ float bfhi(unsigned p){return __uint_as_float(p&0xFFFF0000u);}
__device__ __forceinline__ void mmabf(float* c,unsigned a0,unsigned a1,unsigned a2,unsigned a3,unsigned b0,unsigned b1){
  asm("mma.sync.aligned.m16n8k16.row.col.f32.bf16.bf16.f32 {%0,%1,%2,%3},{%4,%5,%6,%7},{%8,%9},{%0,%1,%2,%3};"
      :"+f"(c[0]),"+f"(c[1]),"+f"(c[2]),"+f"(c[3]):"r"(a0),"r"(a1),"r"(a2),"r"(a3),"r"(b0),"r"(b1));}
__device__ __forceinline__ void cpa16(uint32_t d,const void* s,int sz){
  asm volatile("cp.async.cg.shared.global [%0],[%1],16,%2;"::"r"(d),"l"(s),"r"(sz));}
__device__ __forceinline__ void cpacommit(){asm volatile("cp.async.commit_group;");}
template<int N> __device__ __forceinline__ void cpawait(){asm volatile("cp.async.wait_group %0;"::"n"(N));}

template<int NT>
__device__ __forceinline__ void mma_sweepN(const float* A,const uint2* Wh,const uint2* Wl,
    int KT,float C[][4],int mrow,int tq,int stride){
  const int lane=threadIdx.x&31;
  for(int kt=0;kt<KT;kt++){
    const float* ap=A+mrow*stride+kt*16+2*tq;
    float2 x0=*(const float2*)ap;
    float2 x1=*(const float2*)(ap+8*stride);
    float2 x2=*(const float2*)(ap+8);
    float2 x3=*(const float2*)(ap+8*stride+8);
    unsigned a0=packbf(x0.x,x0.y),a1=packbf(x1.x,x1.y),a2=packbf(x2.x,x2.y),a3=packbf(x3.x,x3.y);
    unsigned l0=packbf(x0.x-bflo(a0),x0.y-bfhi(a0)),l1=packbf(x1.x-bflo(a1),x1.y-bfhi(a1));
    unsigned l2=packbf(x2.x-bflo(a2),x2.y-bfhi(a2)),l3=packbf(x3.x-bflo(a3),x3.y-bfhi(a3));
    #pragma unroll
    for(int nt=0;nt<NT;nt++){
      int s=(kt*NT+nt)*32+lane;
      uint2 bh=Wh[s],bl=Wl[s];
      mmabf(C[nt],a0,a1,a2,a3,bh.x,bh.y);
      mmabf(C[nt],a0,a1,a2,a3,bl.x,bl.y);
      mmabf(C[nt],l0,l1,l2,l3,bh.x,bh.y);
    }
  }
}

__device__ __forceinline__ void sweep_pk(const unsigned* Ah,const unsigned* Al,
    const uint2* Wh,const uint2* Wl,int KT,float C[][4],int mrow,int tq){
  const int lane=threadIdx.x&31;
  for(int kt=0;kt<KT;kt++){
    int i0=mrow*36+kt*8+tq;
    unsigned a0=Ah[i0],a1=Ah[i0+288],a2=Ah[i0+4],a3=Ah[i0+292];
    unsigned l0=Al[i0],l1=Al[i0+288],l2=Al[i0+4],l3=Al[i0+292];
    #pragma unroll
    for(int nt=0;nt<8;nt++){
      int s=(kt*8+nt)*32+lane;
      uint2 bh=Wh[s],bl=Wl[s];
      mmabf(C[nt],a0,a1,a2,a3,bh.x,bh.y);
      mmabf(C[nt],a0,a1,a2,a3,bl.x,bl.y);
      mmabf(C[nt],l0,l1,l2,l3,bh.x,bh.y);
    }
  }
}

#define PREP_BODY(NSLOT,NT,BASE,GET) \
  for(int s=threadIdx.x;s<(NSLOT);s+=256){ \
    int lane=s&31,wd=s>>5,nt=wd%(NT),kt=wd/(NT); \
    int nn=nt*8+(lane>>2),k0=kt*16+(lane&3)*2; \
    float w00=GET(k0,nn),w01=GET((k0+1),nn),w10=GET((k0+8),nn),w11=GET((k0+9),nn); \
    unsigned h0=packbf(w00,w01),h1=packbf(w10,w11); \
    g_wf[(BASE)+s]=make_uint2(h0,h1); \
    g_wf[(BASE)+(NSLOT)+s]=make_uint2(packbf(w00-bflo(h0),w01-bfhi(h0)),packbf(w10-bflo(h1),w11-bfhi(h1))); \
  }

__global__ void k_prep_all(const float* __restrict__ cw,const float* __restrict__ w0,
    const float* __restrict__ w1m,const float* __restrict__ w2m,
    const float* __restrict__ w1f,const float* __restrict__ w2f){
  int bb=blockIdx.x;
  if(bb<20){
    int l=bb>>2,p=bb&3;
    const float* w=cw+l*16384;
    #define G(kk,nn) (w[(nn)*256+(kk)*4+p])
    PREP_BODY(1024,8,bb*2048,G)
    #undef G
  } else if(bb==20){
    #define G(kk,nn) (((kk)<12)?w0[(nn)*12+(kk)]:0.f)
    PREP_BODY(256,8,40960,G)
    #undef G
  } else if(bb<37){
    int i=bb-21,l=i>>2,u=i&3;
    const float* wp=(u<3)?(w1m+l*12288+u*4096):(w2m+l*4096);
    #define G(kk,nn) (wp[(kk)*64+(nn)])
    PREP_BODY(1024,8,41472+i*2048,G)
    #undef G
  } else {
    int bf=bb-37;
    if(bf<2){
      #define G(kk,nn) (w1f[((bf)*64+(kk))*128+(nn)])
      PREP_BODY(2048,16,74240+bf*4096,G)
      #undef G
    } else if(bf==2){
      #define G(kk,nn) (((kk)<6)?w1f[(128+(kk))*128+(nn)]:0.f)
      PREP_BODY(512,16,82432,G)
      #undef G
    } else {
      #define G(kk,nn) (w2f[(kk)*64+(nn)])
      PREP_BODY(2048,8,83456,G)
      #undef G
    }
  }
}

__device__ __forceinline__ void issueWF(uint2* buf,int gbase,int n){
  uint32_t db=(uint32_t)__cvta_generic_to_shared(buf);
  const uint2* src=g_wf+gbase;
  for(int j=threadIdx.x*2;j<n;j+=512) cpa16(db+j*8,src+j,16);
}

// ===== conv0+conv1 (L0), occ2, as R16 =======================================
__global__ void __launch_bounds__(256,2) k_cnn(const float* __restrict__ crop,
    unsigned* __restrict__ oh,unsigned* __restrict__ ol,
    const float* __restrict__ b0c,const float* __restrict__ b){
  extern __shared__ float sm[];
  uint2* Wb0=(uint2*)sm;
  uint2* Wb1=Wb0+2048;
  float* b0s=(float*)(Wb1+2048);
  float* bs=b0s+64;
  unsigned* A0h=(unsigned*)(bs+64);
  unsigned* A0l=A0h+4608;
  unsigned* A1h=A0l+4608;
  float* cropw=(float*)A1h;
  float* Ap=cropw+6144;
  uint2* W0f=(uint2*)(Ap+2560);
  const int t=threadIdx.x,lane=t&31,wid=t>>5;
  const int Rbase=blockIdx.x*128;
  const int half=(Rbase>>7)&1;
  const int g=lane>>2,tq=lane&3,mrow=wid*16+g;
  if(t<64){bs[t]=b[t];b0s[t]=b0c[t];}
  issueWF(W0f,40960,512);
  {
    int n=Rbase>>8;
    uint32_t db=(uint32_t)__cvta_generic_to_shared(cropw);
    for(int i=t*4;i<6144;i+=1024){
      int c=i>>11,r=i&2047,y=r>>6,xx=r&63;
      cpa16(db+i*4,&crop[(((size_t)n*3+c)*64+half*32+y)*64+xx],16);
    }
  }
  issueWF(Wb0,0*2048,2048);
  cpacommit();
  float C[8][4];
  #pragma unroll
  for(int i=0;i<8;i++){C[i][0]=0;C[i][1]=0;C[i][2]=0;C[i][3]=0;}
  for(int p=0;p<4;p++){
    if(p<3){issueWF((p&1)?Wb0:Wb1,(p+1)*2048,2048);cpacommit();}
    if(p<3)cpawait<1>();else cpawait<0>();
    __syncthreads();
    const int ky=p>>1,kx=p&1;
    for(int i=t;i<2048;i+=256){
      int row=i>>4,col=i&15; float v=0.f;
      if(col<12){
        int sp=(Rbase+row)&255,oy=sp>>4,ox=sp&15;
        int oyl=oy-half*8;
        int c=col>>2,q=col&3;
        v=cropw[c*2048+(4*oyl+2*ky+(q>>1))*64+4*ox+2*kx+(q&1)];
      }
      Ap[row*20+col]=v;
    }
    __syncthreads();
    float C0[8][4];
    #pragma unroll
    for(int i=0;i<8;i++){C0[i][0]=0;C0[i][1]=0;C0[i][2]=0;C0[i][3]=0;}
    mma_sweepN<8>(Ap,W0f,W0f+256,1,C0,mrow,tq,20);
    #pragma unroll
    for(int nt=0;nt<8;nt++){
      int col=nt*8+tq*2,kp=nt*4+tq;
      float v00=fmaxf(C0[nt][0]+b0s[col],0.f),v01=fmaxf(C0[nt][1]+b0s[col+1],0.f);
      float v10=fmaxf(C0[nt][2]+b0s[col],0.f),v11=fmaxf(C0[nt][3]+b0s[col+1],0.f);
      unsigned h0=packbf(v00,v01);
      A0h[mrow*36+kp]=h0; A0l[mrow*36+kp]=packbf(v00-bflo(h0),v01-bfhi(h0));
      unsigned h1=packbf(v10,v11);
      A0h[(mrow+8)*36+kp]=h1; A0l[(mrow+8)*36+kp]=packbf(v10-bflo(h1),v11-bfhi(h1));
    }
    __syncthreads();
    sweep_pk(A0h,A0l,(p&1)?Wb1:Wb0,((p&1)?Wb1:Wb0)+1024,4,C,mrow,tq);
    __syncthreads();
  }
  #pragma unroll
  for(int nt=0;nt<8;nt++){
    int col=nt*8+tq*2,kp=nt*4+tq;
    size_t r0=Rbase+mrow,r1=r0+8;
    float v00=fmaxf(C[nt][0]+bs[col],0.f),v01=fmaxf(C[nt][1]+bs[col+1],0.f);
    float v10=fmaxf(C[nt][2]+bs[col],0.f),v11=fmaxf(C[nt][3]+bs[col+1],0.f);
    unsigned h=packbf(v00,v01);
    oh[r0*32+kp]=h; ol[r0*32+kp]=packbf(v00-bflo(h),v01-bfhi(h));
    h=packbf(v10,v11);
    oh[r1*32+kp]=h; ol[r1*32+kp]=packbf(v10-bflo(h),v11-bfhi(h));
  }
}

// ===== conv layers 1..4, occ3, single A buffer ==============================
__global__ void __launch_bounds__(256,3) k_cnnN(
    const unsigned* __restrict__ inh,const unsigned* __restrict__ inl,
    unsigned* __restrict__ oh,unsigned* __restrict__ ol,float* __restrict__ outf,
    const float* __restrict__ b,int so_bits,int M,int outPk,int lidx){
  extern __shared__ float sm[];
  uint2* Wb0=(uint2*)sm; uint2* Wb1=Wb0+2048;
  float* bs=(float*)(Wb1+2048);
  unsigned* Ah=(unsigned*)(bs+64);
  unsigned* Al=Ah+4608;
  const int t=threadIdx.x,lane=t&31,wid=t>>5;
  const int Rbase=blockIdx.x*128;
  const int S_out=1<<so_bits,S_in=S_out<<1,so2=so_bits*2;
  const int g=lane>>2,tq=lane&3,mrow=wid*16+g;
  const int wfb=lidx*4;
  if(t<64)bs[t]=b[t];
  auto issueA=[&](int pp){
    int ky_=pp>>1,kx_=pp&1;
    uint32_t dbh=(uint32_t)__cvta_generic_to_shared(Ah);
    uint32_t dbl=(uint32_t)__cvta_generic_to_shared(Al);
    #pragma unroll
    for(int k_=0;k_<8;k_++){
      int idx=t+k_*256;
      int pl=idx>>10,id2=idx&1023;
      int row=id2>>3,j=(id2&7)*4;
      int R=Rbase+row;
      const unsigned* sp_=inh; int sz_=0;
      if(R<M){
        int n_=R>>so2,s2=R&(S_out*S_out-1),oy_=s2>>so_bits,ox_=s2&(S_out-1);
        size_t go=((size_t)((n_*S_in+2*oy_+ky_)*S_in)+2*ox_+kx_)*32+j;
        sp_=(pl?inl:inh)+go; sz_=16;
      }
      cpa16((pl?dbl:dbh)+(row*36+j)*4,sp_,sz_);
    }
  };
  issueA(0);
  issueWF(Wb0,wfb*2048,2048);
  cpacommit();
  float C[8][4];
  #pragma unroll
  for(int i=0;i<8;i++){C[i][0]=0;C[i][1]=0;C[i][2]=0;C[i][3]=0;}
  for(int p=0;p<4;p++){
    if(p<3){
      issueWF((p&1)?Wb0:Wb1,(wfb+p+1)*2048,2048);
      cpacommit();
      cpawait<1>();
    } else cpawait<0>();
    __syncthreads();
    sweep_pk(Ah,Al,(p&1)?Wb1:Wb0,((p&1)?Wb1:Wb0)+1024,4,C,mrow,tq);
    __syncthreads();
    if(p<3){issueA(p+1);cpacommit();}
  }
  #pragma unroll
  for(int nt=0;nt<8;nt++){
    int col=nt*8+tq*2,kp=nt*4+tq,r0=Rbase+mrow,r1=r0+8;
    float v00=fmaxf(C[nt][0]+bs[col],0.f),v01=fmaxf(C[nt][1]+bs[col+1],0.f);
    float v10=fmaxf(C[nt][2]+bs[col],0.f),v11=fmaxf(C[nt][3]+bs[col+1],0.f);
    if(outPk){
      if(r0<M){unsigned h=packbf(v00,v01);
        oh[(size_t)r0*32+kp]=h; ol[(size_t)r0*32+kp]=packbf(v00-bflo(h),v01-bfhi(h));}
      if(r1<M){unsigned h=packbf(v10,v11);
        oh[(size_t)r1*32+kp]=h; ol[(size_t)r1*32+kp]=packbf(v10-bflo(h),v11-bfhi(h));}
    } else {
      if(r0<M){float2 v;v.x=v00;v.y=v01;*(float2*)&outf[(size_t)r0*64+col]=v;}
      if(r1<M){float2 v;v.x=v10;v.y=v11;*(float2*)&outf[(size_t)r1*64+col]=v;}
    }
  }
}

// ====== msg MLP + scatter-add, occ3, single A buffer ========================
__global__ void __launch_bounds__(256,3) k_msg(const float* __restrict__ node,
    const float* __restrict__ edge,const int* __restrict__ ei,
    const float* __restrict__ b1,const float* __restrict__ b2,
    int mbase,float* __restrict__ agg){
  extern __shared__ float sm[];
  uint2* Wb0=(uint2*)sm; uint2* Wb1=Wb0+2048;
  float* b1s=(float*)(Wb1+2048); float* b2s=b1s+64;
  float* A0=b2s+64;                     // 8704
  int* srcs=(int*)(A0+8704); int* dsts=srcs+128;
  const int t=threadIdx.x,lane=t&31,wid=t>>5;
  const int ebase=blockIdx.x*128;
  if(t<64){b1s[t]=b1[t];b2s[t]=b2[t];}
  if(t<128){srcs[t]=ei[ebase+t];dsts[t]=ei[EE+ebase+t];}
  const int g=lane>>2,tq=lane&3,mrow=wid*16+g;
  __syncthreads();
  auto issueM=[&](int ch){
    uint32_t db=(uint32_t)__cvta_generic_to_shared(A0);
    #pragma unroll
    for(int k_=0;k_<8;k_++){
      int idx=t+k_*256,row=idx>>4,c4=(idx&15)*4;
      const float* s_=(ch==0)?&node[(size_t)dsts[row]*64+c4]:(ch==1)?&node[(size_t)srcs[row]*64+c4]
                     :&edge[(size_t)(ebase+row)*64+c4];
      cpa16(db+(row*68+c4)*4,s_,16);
    }
  };
  float C1[8][4];
  #pragma unroll
  for(int i=0;i<8;i++){C1[i][0]=0;C1[i][1]=0;C1[i][2]=0;C1[i][3]=0;}
  issueM(0);issueWF(Wb0,mbase,2048);cpacommit();
  for(int ch=0;ch<3;ch++){
    issueWF((ch&1)?Wb0:Wb1,mbase+(ch+1)*2048,2048);
    cpacommit();
    cpawait<1>();
    __syncthreads();
    mma_sweepN<8>(A0,(ch&1)?Wb1:Wb0,((ch&1)?Wb1:Wb0)+1024,4,C1,mrow,tq,68);
    __syncthreads();
    if(ch<2){issueM(ch+1);cpacommit();}
  }
  // H = relu(C1+b1) into A0
  #pragma unroll
  for(int nt=0;nt<8;nt++){
    int col=nt*8+tq*2;
    A0[mrow*68+col]=fmaxf(C1[nt][0]+b1s[col],0.f);
    A0[mrow*68+col+1]=fmaxf(C1[nt][1]+b1s[col+1],0.f);
    A0[(mrow+8)*68+col]=fmaxf(C1[nt][2]+b1s[col],0.f);
    A0[(mrow+8)*68+col+1]=fmaxf(C1[nt][3]+b1s[col+1],0.f);
  }
  cpawait<0>();
  __syncthreads();
  float C2[8][4];
  #pragma unroll
  for(int i=0;i<8;i++){C2[i][0]=0;C2[i][1]=0;C2[i][2]=0;C2[i][3]=0;}
  mma_sweepN<8>(A0,Wb1,Wb1+1024,4,C2,mrow,tq,68);
  const int d0=dsts[mrow],d1=dsts[mrow+8];
  #pragma unroll
  for(int nt=0;nt<8;nt++){
    int col=nt*8+tq*2;
    atomicAdd(&agg[(size_t)d0*64+col],C2[nt][0]+b2s[col]);
    atomicAdd(&agg[(size_t)d0*64+col+1],C2[nt][1]+b2s[col+1]);
    atomicAdd(&agg[(size_t)d1*64+col],C2[nt][2]+b2s[col]);
    atomicAdd(&agg[(size_t)d1*64+col+1],C2[nt][3]+b2s[col+1]);
  }
}

// --------------------------------------------- node_update: [x|cf]@W + LN
__global__ void __launch_bounds__(256) k_nodeup(const float* __restrict__ x,
    const float* __restrict__ cf, const float* __restrict__ w, const float* __restrict__ b,
    const float* __restrict__ g, const float* __restrict__ be, float* __restrict__ out) {
    extern __shared__ float sm[];
    float* Ws = sm;
    float* Bs = Ws + 6144; float* Gs = Bs + 64; float* BEs = Gs + 64;
    float* mu = BEs + 64; float* rs = mu + 64;
    float* As = rs + 64; float* Hs = As + 6400;
    int t = threadIdx.x;
    int Rbase = blockIdx.x * 64;
    for (int i = t; i < 6144; i += 256) Ws[i] = w[i];
    if (t < 64) { Bs[t]=b[t]; Gs[t]=g[t]; BEs[t]=be[t]; }
    for (int e = t; e < 2048; e += 256) {
        int row = e >> 5, c = e & 31, nd = Rbase + row;
        As[row * 100 + c] = (nd < NN) ? x[nd * 32 + c] : 0.f;
    }
    for (int e = t; e < 4096; e += 256) {
        int row = e >> 6, c = e & 63, nd = Rbase + row;
        As[row * 100 + 32 + c] = (nd < NN) ? cf[nd * 64 + c] : 0.f;
    }
    __syncthreads();
    int tr = t >> 4, tc = t & 15;
    float acc[4][4];
    float4 b4 = *(const float4*)&Bs[tc * 4];
    #pragma unroll
    for (int i = 0; i < 4; i++) { acc[i][0]=b4.x; acc[i][1]=b4.y; acc[i][2]=b4.z; acc[i][3]=b4.w; }
    for (int k = 0; k < 96; k++) {
        float4 w4 = *(const float4*)&Ws[k * 64 + tc * 4];
        #pragma unroll
        for (int i = 0; i < 4; i++) {
            float a = As[(tr * 4 + i) * 100 + k];
            acc[i][0] += a*w4.x; acc[i][1] += a*w4.y; acc[i][2] += a*w4.z; acc[i][3] += a*w4.w;
        }
    }
    #pragma unroll
    for (int i = 0; i < 4; i++) {
        float4 r; r.x=fmaxf(acc[i][0],0.f); r.y=fmaxf(acc[i][1],0.f);
        r.z=fmaxf(acc[i][2],0.f); r.w=fmaxf(acc[i][3],0.f);
        *(float4*)&Hs[(tr * 4 + i) * 68 + tc * 4] = r;
    }
    __syncthreads();
    if (t < 64) {
        float s = 0.f, sq = 0.f;
        for (int c = 0; c < 64; c++) { float v = Hs[t * 68 + c]; s += v; sq += v * v; }
        float m = s * (1.f / 64.f);
        mu[t] = m; rs[t] = rsqrtf(sq * (1.f / 64.f) - m * m + 1e-5f);
    }
    __syncthreads();
    for (int i = t; i < 4096; i += 256) {
        int r = i >> 6, c = i & 63, nd = Rbase + r;
        if (nd < NN) out[nd * 64 + c] = (Hs[r * 68 + c] - mu[r]) * rs[r] * Gs[c] + BEs[c];
    }
}

// --------------------------------------------- edge_update: ea@W + LN
__global__ void __launch_bounds__(256) k_edgeup(const float* __restrict__ ea,
    const float* __restrict__ w, const float* __restrict__ b,
    const float* __restrict__ g, const float* __restrict__ be, float* __restrict__ out) {
    __shared__ float Ws[384], Bs[64], Gs[64], BEs[64], Aa[64][8], Hs[64][68], mu[64], rs[64];
    int t = threadIdx.x;
    int ebase = blockIdx.x * 64;
    for (int i = t; i < 384; i += 256) Ws[i] = w[i];
    if (t < 64) { Bs[t]=b[t]; Gs[t]=g[t]; BEs[t]=be[t]; }
    for (int e = t; e < 384; e += 256) {
        int row = e / 6, k = e - row * 6;
        Aa[row][k] = ea[(size_t)(ebase + row) * 6 + k];
    }
    __syncthreads();
    int r = t >> 2, cg = (t & 3) * 16;
    float a0=Aa[r][0],a1=Aa[r][1],a2=Aa[r][2],a3=Aa[r][3],a4=Aa[r][4],a5=Aa[r][5];
    #pragma unroll
    for (int j = 0; j < 16; j++) {
        int c = cg + j;
        float h = Bs[c] + a0*Ws[c] + a1*Ws[64+c] + a2*Ws[128+c] + a3*Ws[192+c] + a4*Ws[256+c] + a5*Ws[320+c];
        Hs[r][c] = fmaxf(h, 0.f);
    }
    __syncthreads();
    if (t < 64) {
        float s = 0.f, sq = 0.f;
        for (int c = 0; c < 64; c++) { float v = Hs[t][c]; s += v; sq += v * v; }
        float m = s * (1.f / 64.f);
        mu[t] = m; rs[t] = rsqrtf(sq * (1.f / 64.f) - m * m + 1e-5f);
    }
    __syncthreads();
    for (int i = t; i < 4096; i += 256) {
        int rr = i >> 6, c = i & 63;
        out[(size_t)ebase * 64 + i] = (Hs[rr][c] - mu[rr]) * rs[rr] * Gs[c] + BEs[c];
    }
}

// ========= node MLP: [node|agg] 2-layer, 128 nodes/block =====================
__global__ void __launch_bounds__(256, 2) k_nodemlp(const float* __restrict__ node,
    const float* __restrict__ agg, const float* __restrict__ w1, const float* __restrict__ b1,
    const float* __restrict__ w2, const float* __restrict__ b2, float* __restrict__ out) {
    extern __shared__ float sm[];
    float* W1s = sm;
    float* W2s = W1s + 8192;
    float* B1s = W2s + 4096; float* B2s = B1s + 64;
    float* As = B2s + 64;
    const int t = threadIdx.x;
    const int Rbase = blockIdx.x * 128;
    for (int i = t; i < 8192; i += 256) W1s[i] = w1[i];
    for (int i = t; i < 4096; i += 256) W2s[i] = w2[i];
    if (t < 64) { B1s[t]=b1[t]; B2s[t]=b2[t]; }
    const int tr = t >> 3, tc = t & 7;
    const float* ar[4];
    #pragma unroll
    for (int i = 0; i < 4; i++) ar[i] = &As[(tr * 4 + i) * 65];
    float acc[4][8];
    for (int ch = 0; ch < 2; ch++) {
        __syncthreads();
        for (int e = t * 4; e < 8192; e += 1024) {
            int row = e >> 6, c4 = e & 63, nd = Rbase + row;
            float4 vv = make_float4(0.f,0.f,0.f,0.f);
            if (nd < NN) {
                const float* base = (ch == 0) ? &node[(size_t)nd * 64] : &agg[(size_t)nd * 64];
                vv = *(const float4*)&base[c4];
            }
            float* d = &As[row * 65 + c4];
            d[0]=vv.x; d[1]=vv.y; d[2]=vv.z; d[3]=vv.w;
        }
        __syncthreads();
        if (ch == 0) {
            float4 ba = *(const float4*)&B1s[tc * 8];
            float4 bb = *(const float4*)&B1s[tc * 8 + 4];
            #pragma unroll
            for (int i = 0; i < 4; i++) {
                acc[i][0]=ba.x;acc[i][1]=ba.y;acc[i][2]=ba.z;acc[i][3]=ba.w;
                acc[i][4]=bb.x;acc[i][5]=bb.y;acc[i][6]=bb.z;acc[i][7]=bb.w;
            }
        }
        const float* wp = &W1s[ch * 4096 + tc * 8];
        #pragma unroll 8
        for (int k = 0; k < 64; k++) {
            float4 wa = *(const float4*)&wp[k * 64];
            float4 wb = *(const float4*)&wp[k * 64 + 4];
            #pragma unroll
            for (int i = 0; i < 4; i++) {
                float a = ar[i][k];
                acc[i][0]+=a*wa.x; acc[i][1]+=a*wa.y; acc[i][2]+=a*wa.z; acc[i][3]+=a*wa.w;
                acc[i][4]+=a*wb.x; acc[i][5]+=a*wb.y; acc[i][6]+=a*wb.z; acc[i][7]+=a*wb.w;
            }
        }
    }
    __syncthreads();
    #pragma unroll
    for (int i = 0; i < 4; i++)
        #pragma unroll
        for (int j = 0; j < 8; j++)
            As[(tr * 4 + i) * 65 + tc * 8 + j] = fmaxf(acc[i][j], 0.f);
    __syncthreads();
    float a2[4][8];
    {
        float4 ba = *(const float4*)&B2s[tc * 8];
        float4 bb = *(const float4*)&B2s[tc * 8 + 4];
        #pragma unroll
        for (int i = 0; i < 4; i++) {
            a2[i][0]=ba.x;a2[i][1]=ba.y;a2[i][2]=ba.z;a2[i][3]=ba.w;
            a2[i][4]=bb.x;a2[i][5]=bb.y;a2[i][6]=bb.z;a2[i][7]=bb.w;
        }
    }
    const float* wp2 = &W2s[tc * 8];
    #pragma unroll 8
    for (int k = 0; k < 64; k++) {
        float4 wa = *(const float4*)&wp2[k * 64];
        float4 wb = *(const float4*)&wp2[k * 64 + 4];
        #pragma unroll
        for (int i = 0; i < 4; i++) {
            float a = ar[i][k];
            a2[i][0]+=a*wa.x; a2[i][1]+=a*wa.y; a2[i][2]+=a*wa.z; a2[i][3]+=a*wa.w;
            a2[i][4]+=a*wb.x; a2[i][5]+=a*wb.y; a2[i][6]+=a*wb.z; a2[i][7]+=a*wb.w;
        }
    }
    #pragma unroll
    for (int i = 0; i < 4; i++) {
        int nd = Rbase + tr * 4 + i;
        if (nd < NN) {
            float4 v;
            v.x=a2[i][0]; v.y=a2[i][1]; v.z=a2[i][2]; v.w=a2[i][3];
            *(float4*)&out[(size_t)nd * 64 + tc * 8] = v;
            v.x=a2[i][4]; v.y=a2[i][5]; v.z=a2[i][6]; v.w=a2[i][7];
            *(float4*)&out[(size_t)nd * 64 + tc * 8 + 4] = v;
        }
    }
}

// ===== final edge MLP (classic bf16 mma): 134->128->64->1 ===================
__global__ void __launch_bounds__(256,2) k_final(const float* __restrict__ node,
    const float* __restrict__ ea,const int* __restrict__ ei,
    const float* __restrict__ b1,const float* __restrict__ b2,
    const float* __restrict__ w3,const float* __restrict__ b3,float* __restrict__ out){
  extern __shared__ float sm[];
  uint2* Wb=(uint2*)sm;
  float* B1s=(float*)(Wb+4096);
  float* B2s=B1s+128; float* w3s=B2s+64; float* b3s=w3s+64;
  float* HA=b3s+4;
  int* srcs=(int*)(HA+16896); int* dsts=srcs+128;
  const int t=threadIdx.x,lane=t&31,wid=t>>5;
  const int ebase=blockIdx.x*128;
  if(t<128){B1s[t]=b1[t];srcs[t]=ei[ebase+t];dsts[t]=ei[EE+ebase+t];}
  if(t<64){B2s[t]=b2[t];w3s[t]=w3[t];}
  if(t==0)b3s[0]=b3[0];
  const int g=lane>>2,tq=lane&3,mrow=wid*16+g;
  __syncthreads();
  float C1[16][4];
  #pragma unroll
  for(int i=0;i<16;i++){C1[i][0]=0;C1[i][1]=0;C1[i][2]=0;C1[i][3]=0;}
  for(int ch=0;ch<2;ch++){
    uint32_t db=(uint32_t)__cvta_generic_to_shared(HA);
    #pragma unroll
    for(int k_=0;k_<8;k_++){
      int idx=t+k_*256,row=idx>>4,c4=(idx&15)*4;
      const int nd=(ch==0)?srcs[row]:dsts[row];
      cpa16(db+(row*68+c4)*4,&node[(size_t)nd*64+c4],16);
    }
    issueWF(Wb,74240+ch*4096,4096);
    cpacommit();
    cpawait<0>();
    __syncthreads();
    mma_sweepN<16>(HA,Wb,Wb+2048,4,C1,mrow,tq,68);
    __syncthreads();
  }
  for(int i=t;i<2560;i+=256)HA[i]=0.f;
  issueWF(Wb,82432,1024);
  cpacommit();
  __syncthreads();
  for(int i=t;i<768;i+=256){int row=i/6,k=i-row*6;HA[row*20+k]=ea[(size_t)(ebase+row)*6+k];}
  cpawait<0>();
  __syncthreads();
  mma_sweepN<16>(HA,Wb,Wb+512,1,C1,mrow,tq,20);
  __syncthreads();
  issueWF(Wb,83456,4096);
  cpacommit();
  #pragma unroll
  for(int nt=0;nt<16;nt++){
    int col=nt*8+tq*2;
    HA[mrow*132+col]      =fmaxf(C1[nt][0]+B1s[col],0.f);
    HA[mrow*132+col+1]    =fmaxf(C1[nt][1]+B1s[col+1],0.f);
    HA[(mrow+8)*132+col]  =fmaxf(C1[nt][2]+B1s[col],0.f);
    HA[(mrow+8)*132+col+1]=fmaxf(C1[nt][3]+B1s[col+1],0.f);
  }
  cpawait<0>();
  __syncthreads();
  float C2[8][4];
  #pragma unroll
  for(int i=0;i<8;i++){C2[i][0]=0;C2[i][1]=0;C2[i][2]=0;C2[i][3]=0;}
  mma_sweepN<8>(HA,Wb,Wb+2048,8,C2,mrow,tq,132);
  __syncthreads();
  #pragma unroll
  for(int nt=0;nt<8;nt++){
    int col=nt*8+tq*2;
    HA[mrow*68+col]      =fmaxf(C2[nt][0]+B2s[col],0.f);
    HA[mrow*68+col+1]    =fmaxf(C2[nt][1]+B2s[col+1],0.f);
    HA[(mrow+8)*68+col]  =fmaxf(C2[nt][2]+B2s[col],0.f);
    HA[(mrow+8)*68+col+1]=fmaxf(C2[nt][3]+B2s[col+1],0.f);
  }
  __syncthreads();
  if(t<128){
    float s=b3s[0];
    #pragma unroll 8
    for(int c=0;c<64;c++)s+=HA[t*68+c]*w3s[c];
    out[ebase+t]=s;
  }
}

// ============================================================================
extern "C" void kernel_launch(void* const* d_in, const int* in_sizes, int n_in,
                              void* d_out, int out_size) {
    const float *x=0,*ea=0,*crop=0,*cw0=0,*cb0=0,*cw=0,*cb=0,*nu_w=0,*nu_b=0,*nu_g=0,*nu_be=0,
        *eu_w=0,*eu_b=0,*eu_g=0,*eu_be=0,*ie_w1=0,*ie_b1=0,*ie_w2=0,*ie_b2=0,
        *in_w1=0,*in_b1=0,*in_w2=0,*in_b2=0,*em_w1=0,*em_b1=0,*em_w2=0,*em_b2=0,*em_w3=0,*em_b3=0;
    const int* ei = 0;
    int c64 = 0, c256 = 0, c16k = 0;
    for (int i = 0; i < n_in; i++) {
        const float* p = (const float*)d_in[i];
        switch (in_sizes[i]) {
            case 320000: x = p; break;
            case 640000: ei = (const int*)p; break;
            case 1920000: ea = p; break;
            case 122880000: crop = p; break;
            case 768: cw0 = p; break;
            case 81920: cw = p; break;
            case 320: cb = p; break;
            case 6144: nu_w = p; break;
            case 384: eu_w = p; break;
            case 49152: ie_w1 = p; break;
            case 32768: in_w1 = p; break;
            case 17152: em_w1 = p; break;
            case 128: em_b1 = p; break;
            case 8192: em_w2 = p; break;
            case 1: em_b3 = p; break;
            case 16384: if (c16k++ == 0) ie_w2 = p; else in_w2 = p; break;
            case 256:
                if (c256 == 0) ie_b1 = p; else if (c256 == 1) ie_b2 = p;
                else if (c256 == 2) in_b1 = p; else in_b2 = p;
                c256++; break;
            case 64: {
                const float** slots[9] = {&cb0,&nu_b,&nu_g,&nu_be,&eu_b,&eu_g,&eu_be,&em_b2,&em_w3};
                if (c64 < 9) *slots[c64] = p;
                c64++; break;
            }
            default: break;
        }
    }
    unsigned *h1,*l1,*h0,*l0;
    float *cf,*nA,*nB,*agg,*edg;
    cudaGetSymbolAddress((void**)&h1, g_h1);
    cudaGetSymbolAddress((void**)&l1, g_l1);
    cudaGetSymbolAddress((void**)&h0, g_h0);
    cudaGetSymbolAddress((void**)&l0, g_l0);
    cudaGetSymbolAddress((void**)&cf, g_cf);
    cudaGetSymbolAddress((void**)&nA, g_nA);
    cudaGetSymbolAddress((void**)&nB, g_nB);
    cudaGetSymbolAddress((void**)&agg, g_agg);
    cudaGetSymbolAddress((void**)&edg, g_edge);

    const int SM_CNN = 27264 * 4;
    const int SM_CN  = (8192 + 64 + 9216) * 4;
    const int SM_MSG = (8192 + 128 + 8704 + 256) * 4;
    const int SM_NU  = (6144 + 64 * 5 + 6400 + 4352 + 64) * 4;
    const int SM_NM  = (8192 + 4096 + 128 + 8320) * 4;
    const int SM_FIN = (4096 * 2 + 128 + 64 + 64 + 4 + 16896 + 256) * 4;
    cudaFuncSetAttribute(k_cnn,     cudaFuncAttributeMaxDynamicSharedMemorySize, SM_CNN);
    cudaFuncSetAttribute(k_cnnN,    cudaFuncAttributeMaxDynamicSharedMemorySize, SM_CN);
    cudaFuncSetAttribute(k_msg,     cudaFuncAttributeMaxDynamicSharedMemorySize, SM_MSG);
    cudaFuncSetAttribute(k_nodeup,  cudaFuncAttributeMaxDynamicSharedMemorySize, SM_NU);
    cudaFuncSetAttribute(k_nodemlp, cudaFuncAttributeMaxDynamicSharedMemorySize, SM_NM);
    cudaFuncSetAttribute(k_final,   cudaFuncAttributeMaxDynamicSharedMemorySize, SM_FIN);

    // merged weight fragment prep
    k_prep_all<<<41, 256>>>(cw, cw0, ie_w1, ie_w2, em_w1, em_w2);

    // CNN stack
    k_cnn<<<20000, 256, SM_CNN>>>(crop, h1, l1, cb0, cb);
    k_cnnN<<<5000, 256, SM_CN>>>(h1, l1, h0, l0, 0, cb + 64,  3, NN*64, 1, 1);
    k_cnnN<<<1250, 256, SM_CN>>>(h0, l0, h1, l1, 0, cb + 128, 2, NN*16, 1, 2);
    k_cnnN<<<313,  256, SM_CN>>>(h1, l1, h0, l0, 0, cb + 192, 1, NN*4,  1, 3);
    k_cnnN<<<79,   256, SM_CN>>>(h0, l0, 0, 0,  cf, cb + 256, 0, NN,    0, 4);
    // encoders
    k_nodeup<<<157, 256, SM_NU>>>(x, cf, nu_w, nu_b, nu_g, nu_be, nA);
    k_edgeup<<<5000, 256>>>(ea, eu_w, eu_b, eu_g, eu_be, edg);
    // 4 interaction layers
    float* cur = nA; float* nxt = nB;
    for (int l = 0; l < 4; l++) {
        cudaMemsetAsync(agg, 0, (size_t)NN * 64 * sizeof(float), 0);
        k_msg<<<2500, 256, SM_MSG>>>(cur, edg, ei, ie_b1 + l * 64, ie_b2 + l * 64,
                                     41472 + l * 8192, agg);
        k_nodemlp<<<79, 256, SM_NM>>>(cur, agg, in_w1 + l * 8192, in_b1 + l * 64,
                                      in_w2 + l * 4096, in_b2 + l * 64, nxt);
        float* tmp = cur; cur = nxt; nxt = tmp;
    }
    // final edge MLP
    k_final<<<2500, 256, SM_FIN>>>(cur, ea, ei, em_b1, em_b2, em_w3, em_b3, (float*)d_out);
}